// round 1
// baseline (speedup 1.0000x reference)
#include <cuda_runtime.h>
#include <math.h>

namespace {

constexpr int H    = 128;
constexpr int TB   = 64;     // batch rows per CTA
constexpr int NT   = 256;    // 8 warps; warp w owns rows [8w, 8w+8)
constexpr int NATT = 3;
constexpr int NC   = 10;
constexpr float EPS = 1e-5f;

struct SmemLayout {
    float ws[H * H];     // current weight matrix, ws[k*H + c]
    float hs[TB * H];    // hidden state (persistent across layers)
    float us[TB * H];    // x tile, then u = tanh(h W + b)
    float bias[H];
    float gam[H];
    float bet[H];
    float wct[NC * H];   // classifier weight transposed: wct[c*H + k]
    float bc[NC];
    float pad[2];
};

// tanh with fast-math-invariant precision (abs err ~1e-7):
__device__ __forceinline__ float fast_tanh(float x) {
    float a = fabsf(x);
    float e = __expf(-2.0f * a);
    float t = (1.0f - e) / (1.0f + e);
    return copysignf(t, x);
}

// dst[r][c] = act( src[r][:] @ ws[:][c] + bias[c] ) for this warp's 8 rows.
// Thread layout: warp w -> rows 8w..8w+7, lane l -> cols 4l..4l+3.
template <bool DO_TANH>
__device__ __forceinline__ void gemm_tile(const float* __restrict__ src,
                                          const float* __restrict__ ws,
                                          const float* __restrict__ bias,
                                          float* __restrict__ dst,
                                          int w, int l)
{
    const int c0 = 4 * l;
    const int r0 = 8 * w;
    float acc[8][4];
#pragma unroll
    for (int r = 0; r < 8; ++r) {
        acc[r][0] = bias[c0 + 0];
        acc[r][1] = bias[c0 + 1];
        acc[r][2] = bias[c0 + 2];
        acc[r][3] = bias[c0 + 3];
    }
#pragma unroll 4
    for (int k0 = 0; k0 < H; k0 += 4) {
        float4 w0 = *(const float4*)&ws[(k0 + 0) * H + c0];
        float4 w1 = *(const float4*)&ws[(k0 + 1) * H + c0];
        float4 w2 = *(const float4*)&ws[(k0 + 2) * H + c0];
        float4 w3 = *(const float4*)&ws[(k0 + 3) * H + c0];
#pragma unroll
        for (int r = 0; r < 8; ++r) {
            float4 xv = *(const float4*)&src[(r0 + r) * H + k0];
            acc[r][0] = fmaf(xv.x, w0.x, acc[r][0]);
            acc[r][1] = fmaf(xv.x, w0.y, acc[r][1]);
            acc[r][2] = fmaf(xv.x, w0.z, acc[r][2]);
            acc[r][3] = fmaf(xv.x, w0.w, acc[r][3]);
            acc[r][0] = fmaf(xv.y, w1.x, acc[r][0]);
            acc[r][1] = fmaf(xv.y, w1.y, acc[r][1]);
            acc[r][2] = fmaf(xv.y, w1.z, acc[r][2]);
            acc[r][3] = fmaf(xv.y, w1.w, acc[r][3]);
            acc[r][0] = fmaf(xv.z, w2.x, acc[r][0]);
            acc[r][1] = fmaf(xv.z, w2.y, acc[r][1]);
            acc[r][2] = fmaf(xv.z, w2.z, acc[r][2]);
            acc[r][3] = fmaf(xv.z, w2.w, acc[r][3]);
            acc[r][0] = fmaf(xv.w, w3.x, acc[r][0]);
            acc[r][1] = fmaf(xv.w, w3.y, acc[r][1]);
            acc[r][2] = fmaf(xv.w, w3.z, acc[r][2]);
            acc[r][3] = fmaf(xv.w, w3.w, acc[r][3]);
        }
    }
#pragma unroll
    for (int r = 0; r < 8; ++r) {
        float4 o;
        if (DO_TANH) {
            o.x = fast_tanh(acc[r][0]);
            o.y = fast_tanh(acc[r][1]);
            o.z = fast_tanh(acc[r][2]);
            o.w = fast_tanh(acc[r][3]);
        } else {
            o.x = acc[r][0]; o.y = acc[r][1]; o.z = acc[r][2]; o.w = acc[r][3];
        }
        *(float4*)&dst[(r0 + r) * H + c0] = o;
    }
}

// Rank-1 softmax-attention via 13-term Taylor expansion of exp, + residual + LN.
// Exact identity: out_i = (Σ_k u_i^k S_k) / (Σ_k u_i^k T_k),
//   S_k = (1/k!) Σ_j u_j^k h_j,  T_k = (1/k!) Σ_j u_j^k.  |u|<1 ⇒ remainder < 5e-10.
__device__ __forceinline__ void attn_update(float* __restrict__ hs,
                                            const float* __restrict__ us,
                                            const float* __restrict__ gam,
                                            const float* __restrict__ bet,
                                            int w, int l)
{
    const float cf[13] = {
        1.0f, 1.0f, 0.5f,
        1.6666666666666666e-1f, 4.1666666666666664e-2f, 8.3333333333333332e-3f,
        1.3888888888888889e-3f, 1.9841269841269841e-4f, 2.4801587301587302e-5f,
        2.7557319223985893e-6f, 2.7557319223985888e-7f, 2.5052108385441720e-8f,
        2.0876756987868100e-9f };

#pragma unroll 1
    for (int r8 = 0; r8 < 8; ++r8) {
        const int r = 8 * w + r8;
        float uj[4], hj[4], p[4];
#pragma unroll
        for (int m = 0; m < 4; ++m) {
            uj[m] = us[r * H + l + 32 * m];
            hj[m] = hs[r * H + l + 32 * m];
            p[m] = 1.0f;
        }
        float S[13], T[13];
#pragma unroll
        for (int k = 0; k < 13; ++k) {
            float sv = p[0] * hj[0] + p[1] * hj[1] + p[2] * hj[2] + p[3] * hj[3];
            float tv = p[0] + p[1] + p[2] + p[3];
            p[0] *= uj[0]; p[1] *= uj[1]; p[2] *= uj[2]; p[3] *= uj[3];
#pragma unroll
            for (int o = 16; o > 0; o >>= 1) {
                sv += __shfl_xor_sync(0xffffffffu, sv, o);
                tv += __shfl_xor_sync(0xffffffffu, tv, o);
            }
            S[k] = sv * cf[k];
            T[k] = tv * cf[k];
        }
        float y[4];
#pragma unroll
        for (int m = 0; m < 4; ++m) {
            float u = uj[m];
            float N = S[12], D = T[12];
#pragma unroll
            for (int k = 11; k >= 0; --k) {
                N = fmaf(N, u, S[k]);
                D = fmaf(D, u, T[k]);
            }
            y[m] = hj[m] + N / D;
        }
        // LayerNorm over the 128 elements of this row
        float sum = y[0] + y[1] + y[2] + y[3];
        float sq  = y[0] * y[0] + y[1] * y[1] + y[2] * y[2] + y[3] * y[3];
#pragma unroll
        for (int o = 16; o > 0; o >>= 1) {
            sum += __shfl_xor_sync(0xffffffffu, sum, o);
            sq  += __shfl_xor_sync(0xffffffffu, sq, o);
        }
        float mu  = sum * (1.0f / H);
        float var = sq * (1.0f / H) - mu * mu;
        float rs  = rsqrtf(var + EPS);
#pragma unroll
        for (int m = 0; m < 4; ++m) {
            int j = l + 32 * m;
            hs[r * H + j] = (y[m] - mu) * rs * gam[j] + bet[j];
        }
    }
}

__global__ void __launch_bounds__(NT, 1)
fused_simple_attention(const float* __restrict__ x,
                       const float* __restrict__ W_in,
                       const float* __restrict__ b_in,
                       const float* __restrict__ W_att,
                       const float* __restrict__ b_att,
                       const float* __restrict__ gamma,
                       const float* __restrict__ beta,
                       const float* __restrict__ W_c,
                       const float* __restrict__ b_c,
                       float* __restrict__ out)
{
    extern __shared__ unsigned char smem_raw[];
    SmemLayout& s = *reinterpret_cast<SmemLayout*>(smem_raw);
    const int t = threadIdx.x;
    const int w = t >> 5;
    const int l = t & 31;
    const long row0 = (long)blockIdx.x * TB;

    // Load x tile (warp-private rows, coalesced 512B/row) into us
#pragma unroll
    for (int r8 = 0; r8 < 8; ++r8) {
        int r = 8 * w + r8;
        *(float4*)&s.us[r * H + 4 * l] =
            *(const float4*)&x[(row0 + r) * H + 4 * l];
    }
    // Cooperative loads: W_in, b_in, classifier weights (transposed) + bias
    for (int idx = t; idx < H * H / 4; idx += NT)
        ((float4*)s.ws)[idx] = ((const float4*)W_in)[idx];
    if (t < H) s.bias[t] = b_in[t];
    for (int idx = t; idx < H * NC; idx += NT) {
        int k = idx / NC, c = idx - k * NC;
        s.wct[c * H + k] = W_c[idx];
    }
    if (t < NC) s.bc[t] = b_c[t];
    __syncthreads();

    // h = x @ W_in + b_in
    gemm_tile<false>(s.us, s.ws, s.bias, s.hs, w, l);

    for (int i = 0; i < NATT; ++i) {
        __syncthreads();   // all warps done reading previous ws
        const float* Wi = W_att + (size_t)i * H * H;
        for (int idx = t; idx < H * H / 4; idx += NT)
            ((float4*)s.ws)[idx] = ((const float4*)Wi)[idx];
        if (t < H) {
            s.bias[t] = b_att[i * H + t];
            s.gam[t]  = gamma[i * H + t];
            s.bet[t]  = beta[i * H + t];
        }
        __syncthreads();
        // u = tanh(h @ W_att[i] + b_att[i]); then attention+residual+LN (warp-private)
        gemm_tile<true>(s.hs, s.ws, s.bias, s.us, w, l);
        attn_update(s.hs, s.us, s.gam, s.bet, w, l);
    }

    // Classifier: logits = h @ W_c + b_c   (warp-private rows)
#pragma unroll 1
    for (int r8 = 0; r8 < 8; ++r8) {
        int r = 8 * w + r8;
        float4 h4 = *(const float4*)&s.hs[r * H + 4 * l];
        float a[NC];
#pragma unroll
        for (int c = 0; c < NC; ++c) {
            float4 w4 = *(const float4*)&s.wct[c * H + 4 * l];
            a[c] = h4.x * w4.x + h4.y * w4.y + h4.z * w4.z + h4.w * w4.w;
        }
#pragma unroll
        for (int c = 0; c < NC; ++c) {
            float v = a[c];
#pragma unroll
            for (int o = 16; o > 0; o >>= 1)
                v += __shfl_down_sync(0xffffffffu, v, o);
            a[c] = v;
        }
        if (l == 0) {
#pragma unroll
            for (int c = 0; c < NC; ++c)
                out[(row0 + r) * NC + c] = a[c] + s.bc[c];
        }
    }
}

}  // namespace

extern "C" void kernel_launch(void* const* d_in, const int* in_sizes, int n_in,
                              void* d_out, int out_size)
{
    const float* x     = (const float*)d_in[0];
    const float* W_in  = (const float*)d_in[1];
    const float* b_in  = (const float*)d_in[2];
    const float* W_att = (const float*)d_in[3];
    const float* b_att = (const float*)d_in[4];
    const float* gamma = (const float*)d_in[5];
    const float* beta  = (const float*)d_in[6];
    const float* W_c   = (const float*)d_in[7];
    const float* b_c   = (const float*)d_in[8];
    float* out = (float*)d_out;

    const int B = in_sizes[0] / H;
    const int grid = B / TB;                    // B = 16384 -> 256 CTAs
    const int smem = (int)sizeof(SmemLayout);   // ~135 KB dynamic SMEM

    cudaFuncSetAttribute(fused_simple_attention,
                         cudaFuncAttributeMaxDynamicSharedMemorySize, smem);
    fused_simple_attention<<<grid, NT, smem>>>(x, W_in, b_in, W_att, b_att,
                                               gamma, beta, W_c, b_c, out);
}

// round 2
// speedup vs baseline: 1.0178x; 1.0178x over previous
#include <cuda_runtime.h>
#include <math.h>

namespace {

constexpr int H    = 128;
constexpr int TB   = 64;     // batch rows per CTA
constexpr int NT   = 512;    // 16 warps; warp w owns rows [4w, 4w+4)
constexpr int NATT = 3;
constexpr int NC   = 10;
constexpr int NK   = 11;     // Taylor terms (truncation < 3e-8)
constexpr float EPS = 1e-5f;

typedef unsigned long long ull;

struct SmemLayout {
    float ws[H * H];         // current weight matrix, ws[k*H + c]     (64 KB)
    float hd[TB * 2 * H];    // hidden state, duplicated pairs         (64 KB)
    float ud[TB * 2 * H];    // x tile / u = tanh(.), duplicated pairs (64 KB)
    float bias[H];
    float gam[H];
    float bet[H];
    float wct[NC * H];       // classifier weight transposed
    float bc[NC];
    float pad[2];
};

// packed dual-FMA: d.lo += a.lo*b.lo ; d.hi += a.hi*b.hi  (full-rate FP32 path)
__device__ __forceinline__ void fma2(ull& d, ull a, ull b) {
    asm("fma.rn.f32x2 %0, %1, %2, %0;" : "+l"(d) : "l"(a), "l"(b));
}
__device__ __forceinline__ float lo32(ull v) { return __uint_as_float((unsigned)v); }
__device__ __forceinline__ float hi32(ull v) { return __uint_as_float((unsigned)(v >> 32)); }

// tanh with fast-math-invariant precision (abs err ~1e-7):
__device__ __forceinline__ float fast_tanh(float x) {
    float a = fabsf(x);
    float e = __expf(-2.0f * a);
    float t = (1.0f - e) / (1.0f + e);
    return copysignf(t, x);
}

// dst[r][c] = act( src[r][:] @ ws[:][c] + bias[c] ) for this warp's 4 rows.
// src/dst are in duplicated-pair layout (stride 2H, each value stored twice).
// Thread layout: warp w -> rows 4w..4w+3, lane l -> cols 4l..4l+3 as 2 f32x2.
template <bool DO_TANH>
__device__ __forceinline__ void gemm2(const float* __restrict__ src,
                                      const float* __restrict__ ws,
                                      const float* __restrict__ bias,
                                      float* __restrict__ dst,
                                      int w, int l)
{
    const int c0 = 4 * l;
    const int r0 = 4 * w;
    ull acc[4][2];
    ulonglong2 b2 = *(const ulonglong2*)&bias[c0];   // {b[c0],b[c0+1]},{b[c0+2],b[c0+3]}
#pragma unroll
    for (int r = 0; r < 4; ++r) { acc[r][0] = b2.x; acc[r][1] = b2.y; }

#pragma unroll 4
    for (int k0 = 0; k0 < H; k0 += 4) {
        ulonglong2 w0 = *(const ulonglong2*)&ws[(k0 + 0) * H + c0];
        ulonglong2 w1 = *(const ulonglong2*)&ws[(k0 + 1) * H + c0];
        ulonglong2 w2 = *(const ulonglong2*)&ws[(k0 + 2) * H + c0];
        ulonglong2 w3 = *(const ulonglong2*)&ws[(k0 + 3) * H + c0];
#pragma unroll
        for (int r = 0; r < 4; ++r) {
            const float* sp = &src[(r0 + r) * (2 * H) + 2 * k0];
            ulonglong2 x01 = *(const ulonglong2*)sp;        // {x0,x0},{x1,x1} broadcast
            ulonglong2 x23 = *(const ulonglong2*)(sp + 4);  // {x2,x2},{x3,x3}
            fma2(acc[r][0], x01.x, w0.x); fma2(acc[r][1], x01.x, w0.y);
            fma2(acc[r][0], x01.y, w1.x); fma2(acc[r][1], x01.y, w1.y);
            fma2(acc[r][0], x23.x, w2.x); fma2(acc[r][1], x23.x, w2.y);
            fma2(acc[r][0], x23.y, w3.x); fma2(acc[r][1], x23.y, w3.y);
        }
    }
#pragma unroll
    for (int r = 0; r < 4; ++r) {
        float t0 = lo32(acc[r][0]), t1 = hi32(acc[r][0]);
        float t2 = lo32(acc[r][1]), t3 = hi32(acc[r][1]);
        if (DO_TANH) {
            t0 = fast_tanh(t0); t1 = fast_tanh(t1);
            t2 = fast_tanh(t2); t3 = fast_tanh(t3);
        }
        float* dp = &dst[(r0 + r) * (2 * H) + 2 * c0];
        *(float4*)dp       = make_float4(t0, t0, t1, t1);
        *(float4*)(dp + 4) = make_float4(t2, t2, t3, t3);
    }
}

// Rank-1 softmax-attention via NK-term Taylor expansion of exp, + residual + LN.
// out_i = (Σ_k u_i^k S_k)/(Σ_k u_i^k T_k), S_k=(1/k!)Σ_j u_j^k h_j, T_k=(1/k!)Σ_j u_j^k.
__device__ __forceinline__ void attn_update(float* __restrict__ hd,
                                            const float* __restrict__ ud,
                                            const float* __restrict__ gam,
                                            const float* __restrict__ bet,
                                            int w, int l)
{
    const float cf[NK] = {
        1.0f, 1.0f, 0.5f,
        1.6666666666666666e-1f, 4.1666666666666664e-2f, 8.3333333333333332e-3f,
        1.3888888888888889e-3f, 1.9841269841269841e-4f, 2.4801587301587302e-5f,
        2.7557319223985893e-6f, 2.7557319223985888e-7f };

#pragma unroll 1
    for (int r8 = 0; r8 < 4; ++r8) {
        const int r = 4 * w + r8;
        float uj[4], hj[4], p[4];
#pragma unroll
        for (int m = 0; m < 4; ++m) {
            uj[m] = ud[r * (2 * H) + 2 * (l + 32 * m)];
            hj[m] = hd[r * (2 * H) + 2 * (l + 32 * m)];
            p[m] = 1.0f;
        }
        float S[NK], T[NK];
#pragma unroll
        for (int k = 0; k < NK; ++k) {
            float sv = p[0] * hj[0] + p[1] * hj[1] + p[2] * hj[2] + p[3] * hj[3];
            float tv = p[0] + p[1] + p[2] + p[3];
            p[0] *= uj[0]; p[1] *= uj[1]; p[2] *= uj[2]; p[3] *= uj[3];
#pragma unroll
            for (int o = 16; o > 0; o >>= 1) {
                sv += __shfl_xor_sync(0xffffffffu, sv, o);
                tv += __shfl_xor_sync(0xffffffffu, tv, o);
            }
            S[k] = sv * cf[k];
            T[k] = tv * cf[k];
        }
        float y[4];
#pragma unroll
        for (int m = 0; m < 4; ++m) {
            float u = uj[m];
            float N = S[NK - 1], D = T[NK - 1];
#pragma unroll
            for (int k = NK - 2; k >= 0; --k) {
                N = fmaf(N, u, S[k]);
                D = fmaf(D, u, T[k]);
            }
            y[m] = hj[m] + N / D;
        }
        float sum = y[0] + y[1] + y[2] + y[3];
        float sq  = y[0] * y[0] + y[1] * y[1] + y[2] * y[2] + y[3] * y[3];
#pragma unroll
        for (int o = 16; o > 0; o >>= 1) {
            sum += __shfl_xor_sync(0xffffffffu, sum, o);
            sq  += __shfl_xor_sync(0xffffffffu, sq, o);
        }
        float mu  = sum * (1.0f / H);
        float rs  = rsqrtf(sq * (1.0f / H) - mu * mu + EPS);
#pragma unroll
        for (int m = 0; m < 4; ++m) {
            int j = l + 32 * m;
            float v = (y[m] - mu) * rs * gam[j] + bet[j];
            hd[r * (2 * H) + 2 * j]     = v;
            hd[r * (2 * H) + 2 * j + 1] = v;
        }
    }
}

__global__ void __launch_bounds__(NT, 1)
fused_simple_attention(const float* __restrict__ x,
                       const float* __restrict__ W_in,
                       const float* __restrict__ b_in,
                       const float* __restrict__ W_att,
                       const float* __restrict__ b_att,
                       const float* __restrict__ gamma,
                       const float* __restrict__ beta,
                       const float* __restrict__ W_c,
                       const float* __restrict__ b_c,
                       float* __restrict__ out)
{
    extern __shared__ unsigned char smem_raw[];
    SmemLayout& s = *reinterpret_cast<SmemLayout*>(smem_raw);
    const int t = threadIdx.x;
    const int w = t >> 5;
    const int l = t & 31;
    const long row0 = (long)blockIdx.x * TB;

    // Load x tile (warp-private rows, coalesced) into ud in duplicated layout
#pragma unroll
    for (int r8 = 0; r8 < 4; ++r8) {
        int r = 4 * w + r8;
        float4 xv = *(const float4*)&x[(row0 + r) * H + 4 * l];
        float* dp = &s.ud[r * (2 * H) + 8 * l];
        *(float4*)dp       = make_float4(xv.x, xv.x, xv.y, xv.y);
        *(float4*)(dp + 4) = make_float4(xv.z, xv.z, xv.w, xv.w);
    }
    // Cooperative loads: W_in, b_in, classifier weights (transposed) + bias
    for (int idx = t; idx < H * H / 4; idx += NT)
        ((float4*)s.ws)[idx] = ((const float4*)W_in)[idx];
    if (t < H) s.bias[t] = b_in[t];
    for (int idx = t; idx < H * NC; idx += NT) {
        int k = idx / NC, c = idx - k * NC;
        s.wct[c * H + k] = W_c[idx];
    }
    if (t < NC) s.bc[t] = b_c[t];
    __syncthreads();

    // h = x @ W_in + b_in
    gemm2<false>(s.ud, s.ws, s.bias, s.hd, w, l);

    for (int i = 0; i < NATT; ++i) {
        __syncthreads();   // all warps done reading previous ws
        const float* Wi = W_att + (size_t)i * H * H;
        for (int idx = t; idx < H * H / 4; idx += NT)
            ((float4*)s.ws)[idx] = ((const float4*)Wi)[idx];
        if (t < H) {
            s.bias[t] = b_att[i * H + t];
            s.gam[t]  = gamma[i * H + t];
            s.bet[t]  = beta[i * H + t];
        }
        __syncthreads();
        // u = tanh(h @ W_att[i] + b_att[i]); then attention+residual+LN
        gemm2<true>(s.hd, s.ws, s.bias, s.ud, w, l);
        attn_update(s.hd, s.ud, s.gam, s.bet, w, l);
    }

    // Classifier: logits = h @ W_c + b_c   (warp-private rows)
#pragma unroll 1
    for (int r8 = 0; r8 < 4; ++r8) {
        int r = 4 * w + r8;
        const float* hp = &s.hd[r * (2 * H) + 8 * l];
        float h0 = hp[0], h1 = hp[2], h2 = hp[4], h3 = hp[6];
        float a[NC];
#pragma unroll
        for (int c = 0; c < NC; ++c) {
            float4 w4 = *(const float4*)&s.wct[c * H + 4 * l];
            a[c] = h0 * w4.x + h1 * w4.y + h2 * w4.z + h3 * w4.w;
        }
#pragma unroll
        for (int c = 0; c < NC; ++c) {
            float v = a[c];
#pragma unroll
            for (int o = 16; o > 0; o >>= 1)
                v += __shfl_down_sync(0xffffffffu, v, o);
            a[c] = v;
        }
        if (l == 0) {
#pragma unroll
            for (int c = 0; c < NC; ++c)
                out[(row0 + r) * NC + c] = a[c] + s.bc[c];
        }
    }
}

}  // namespace

extern "C" void kernel_launch(void* const* d_in, const int* in_sizes, int n_in,
                              void* d_out, int out_size)
{
    const float* x     = (const float*)d_in[0];
    const float* W_in  = (const float*)d_in[1];
    const float* b_in  = (const float*)d_in[2];
    const float* W_att = (const float*)d_in[3];
    const float* b_att = (const float*)d_in[4];
    const float* gamma = (const float*)d_in[5];
    const float* beta  = (const float*)d_in[6];
    const float* W_c   = (const float*)d_in[7];
    const float* b_c   = (const float*)d_in[8];
    float* out = (float*)d_out;

    const int B = in_sizes[0] / H;
    const int grid = B / TB;                    // B = 16384 -> 256 CTAs
    const int smem = (int)sizeof(SmemLayout);   // ~195 KB dynamic SMEM

    cudaFuncSetAttribute(fused_simple_attention,
                         cudaFuncAttributeMaxDynamicSharedMemorySize, smem);
    fused_simple_attention<<<grid, NT, smem>>>(x, W_in, b_in, W_att, b_att,
                                               gamma, beta, W_c, b_c, out);
}

// round 5
// speedup vs baseline: 2.3335x; 2.2928x over previous
#include <cuda_runtime.h>
#include <cuda_bf16.h>
#include <stdint.h>
#include <math.h>

namespace {
typedef unsigned long long ull;

constexpr int H = 128, NT = 512, NC = 10, NK = 10;
constexpr float EPS = 1e-5f;
constexpr int USP = 132;                     // us row pitch (floats)

// ---- SMEM byte offsets (from 1024-aligned base) ----
constexpr int OFF_AHI  = 0;                  // bf16 A-hi, 2 k-half tiles x 16KB
constexpr int OFF_ALO  = 32768;
constexpr int OFF_BHI  = 65536;              // bf16 B-hi (Bt[n][k]), 2 x 16KB
constexpr int OFF_BLO  = 98304;
constexpr int OFF_US   = 131072;             // float[128][USP]
constexpr int OFF_WC   = OFF_US + 128 * USP * 4;   // float[128][12]
constexpr int OFF_BIAS = OFF_WC + 128 * 12 * 4;    // float[4][128]
constexpr int OFF_GAM  = OFF_BIAS + 4 * 128 * 4;   // float[3][128]
constexpr int OFF_BET  = OFF_GAM + 3 * 128 * 4;
constexpr int OFF_BC   = OFF_BET + 3 * 128 * 4;    // float[16]
constexpr int SMEM_BYTES = OFF_BC + 64 + 1024;

// Pre-converted weights: exact swizzled tile byte layout, one 32KB image per layer.
__device__ __nv_bfloat16 g_bhi[4][16384];
__device__ __nv_bfloat16 g_blo[4][16384];

__host__ __device__ __forceinline__ int swz128(int b) { return b ^ ((b >> 3) & 0x70); }

__device__ __forceinline__ uint32_t smem_u32(const void* p) {
    uint32_t a;
    asm("{ .reg .u64 t; cvta.to.shared.u64 t, %1; cvt.u32.u64 %0, t; }" : "=r"(a) : "l"(p));
    return a;
}

// ---- f32x2 packed math ----
__device__ __forceinline__ ull fma2(ull a, ull b, ull c) {
    ull d; asm("fma.rn.f32x2 %0, %1, %2, %3;" : "=l"(d) : "l"(a), "l"(b), "l"(c)); return d;
}
__device__ __forceinline__ ull add2(ull a, ull b) {
    ull d; asm("add.rn.f32x2 %0, %1, %2;" : "=l"(d) : "l"(a), "l"(b)); return d;
}
__device__ __forceinline__ ull mul2(ull a, ull b) {
    ull d; asm("mul.rn.f32x2 %0, %1, %2;" : "=l"(d) : "l"(a), "l"(b)); return d;
}
__device__ __forceinline__ ull pack2(float lo, float hi) {
    ull d; asm("mov.b64 %0, {%1, %2};" : "=l"(d) : "f"(lo), "f"(hi)); return d;
}
__device__ __forceinline__ float plo(ull v) { return __uint_as_float((unsigned)v); }
__device__ __forceinline__ float phi(ull v) { return __uint_as_float((unsigned)(v >> 32)); }

__device__ __forceinline__ void ldsm4(uint32_t& r0, uint32_t& r1, uint32_t& r2,
                                      uint32_t& r3, uint32_t addr) {
    asm volatile("ldmatrix.sync.aligned.m8n8.x4.shared.b16 {%0,%1,%2,%3}, [%4];"
                 : "=r"(r0), "=r"(r1), "=r"(r2), "=r"(r3) : "r"(addr));
}
__device__ __forceinline__ void mma_bf16(float* c, const uint32_t* a, const uint32_t* b) {
    asm volatile("mma.sync.aligned.m16n8k16.row.col.f32.bf16.bf16.f32 "
                 "{%0,%1,%2,%3}, {%4,%5,%6,%7}, {%8,%9}, {%0,%1,%2,%3};"
                 : "+f"(c[0]), "+f"(c[1]), "+f"(c[2]), "+f"(c[3])
                 : "r"(a[0]), "r"(a[1]), "r"(a[2]), "r"(a[3]), "r"(b[0]), "r"(b[1]));
}

__device__ __forceinline__ float fast_tanh(float x) {
    float a = fabsf(x);
    float e = __expf(-2.0f * a);
    float t = __fdividef(1.0f - e, 1.0f + e);
    return copysignf(t, x);
}
__device__ __forceinline__ void split_bf16(float v, __nv_bfloat16& hi, __nv_bfloat16& lo) {
    hi = __float2bfloat16(v);
    lo = __float2bfloat16(v - __bfloat162float(hi));
}

// One-time: W[k][n] fp32 -> Bt[n][k] bf16 hi/lo in swizzled tile layout.
// Indexing chosen so consecutive threads write consecutive bytes of a line.
__global__ void convert_weights(const float* __restrict__ W_in,
                                const float* __restrict__ W_att) {
    int gidx = blockIdx.x * blockDim.x + threadIdx.x;   // 65536 total
    int layer = gidx >> 14;
    int e = gidx & 16383;
    int n = e >> 7, k = e & 127;
    const float* W = (layer == 0) ? W_in : (W_att + (size_t)(layer - 1) * H * H);
    float v = W[k * H + n];
    __nv_bfloat16 hi, lo;
    split_bf16(v, hi, lo);
    int off = (k >> 6) * 16384 + swz128(n * 128 + (k & 63) * 2);   // bytes
    g_bhi[layer][off >> 1] = hi;
    g_blo[layer][off >> 1] = lo;
}

__device__ __forceinline__ void stage_B(char* sm, int layer, int t) {
    const uint4* sh = (const uint4*)g_bhi[layer];
    const uint4* sl = (const uint4*)g_blo[layer];
    uint4* dh = (uint4*)(sm + OFF_BHI);
    uint4* dl = (uint4*)(sm + OFF_BLO);
#pragma unroll
    for (int i = 0; i < 4; ++i) {
        dh[t + NT * i] = sh[t + NT * i];
        dl[t + NT * i] = sl[t + NT * i];
    }
}

__device__ __forceinline__ void write_A1(char* sm, int row, int col, float v) {
    int byz = (col >> 6) * 16384 + swz128(row * 128 + (col & 63) * 2);
    __nv_bfloat16 hi, lo;
    split_bf16(v, hi, lo);
    *(__nv_bfloat16*)(sm + OFF_AHI + byz) = hi;
    *(__nv_bfloat16*)(sm + OFF_ALO + byz) = lo;
}

__global__ void __launch_bounds__(NT, 1)
fused_kernel(const float* __restrict__ x,
             const float* __restrict__ b_in,
             const float* __restrict__ b_att,
             const float* __restrict__ gamma_,
             const float* __restrict__ beta_,
             const float* __restrict__ W_c,
             const float* __restrict__ b_c,
             float* __restrict__ out)
{
    extern __shared__ char smraw[];
    char* sm = (char*)(((uintptr_t)smraw + 1023) & ~(uintptr_t)1023);
    const int t = threadIdx.x, l = t & 31, w = t >> 5;
    const int wm = w & 3, wn = w >> 2;            // warp tile: rows 32wm.., cols 32wn..
    const int erow = t >> 2, q = t & 3;           // epilogue: row, col residue
    const long row0 = (long)blockIdx.x * 128;
    const uint32_t sbase = smem_u32(sm);

    // ldmatrix per-lane address components (PTX ISA fragment maps)
    const int a_r = l & 15;
    const int a_koff = (l >> 4) * 8;
    const int b_r = (l & 7) + ((l >> 4) * 8);
    const int b_koff = l & 8;

    // ---- init: x -> A tiles, B layer 0, params ----
#pragma unroll
    for (int it = 0; it < 8; ++it) {
        int fidx = t + NT * it;                   // 4096 float4s
        int r = fidx >> 5, c4 = fidx & 31;
        float4 xv = *(const float4*)&x[(row0 + r) * H + 4 * c4];
        int sz = (c4 >> 4) * 16384 + swz128(r * 128 + ((4 * c4) & 63) * 2);
        __nv_bfloat16 h0, h1, h2, h3, l0, l1, l2, l3;
        split_bf16(xv.x, h0, l0); split_bf16(xv.y, h1, l1);
        split_bf16(xv.z, h2, l2); split_bf16(xv.w, h3, l3);
        __nv_bfloat162 ph0; ph0.x = h0; ph0.y = h1;
        __nv_bfloat162 ph1; ph1.x = h2; ph1.y = h3;
        __nv_bfloat162 pl0; pl0.x = l0; pl0.y = l1;
        __nv_bfloat162 pl1; pl1.x = l2; pl1.y = l3;
        *(__nv_bfloat162*)(sm + OFF_AHI + sz)     = ph0;
        *(__nv_bfloat162*)(sm + OFF_AHI + sz + 4) = ph1;
        *(__nv_bfloat162*)(sm + OFF_ALO + sz)     = pl0;
        *(__nv_bfloat162*)(sm + OFF_ALO + sz + 4) = pl1;
    }
    stage_B(sm, 0, t);
    if (t < H) {
        ((float*)(sm + OFF_BIAS))[t] = b_in[t];
#pragma unroll
        for (int i = 0; i < 3; ++i) {
            ((float*)(sm + OFF_BIAS))[(i + 1) * 128 + t] = b_att[i * H + t];
            ((float*)(sm + OFF_GAM))[i * 128 + t] = gamma_[i * H + t];
            ((float*)(sm + OFF_BET))[i * 128 + t] = beta_[i * H + t];
        }
    }
    for (int idx = t; idx < 128 * 12; idx += NT) {
        int col = idx / 12, c = idx % 12;
        ((float*)(sm + OFF_WC))[idx] = (c < NC) ? W_c[col * NC + c] : 0.0f;
    }
    if (t < NC) ((float*)(sm + OFF_BC))[t] = b_c[t];
    __syncthreads();

    const float cf[NK] = {
        1.0f, 1.0f, 0.5f,
        1.6666666666666666e-1f, 4.1666666666666664e-2f, 8.3333333333333332e-3f,
        1.3888888888888889e-3f, 1.9841269841269841e-4f, 2.4801587301587302e-5f,
        2.7557319223985893e-6f };

    ull hp[16];                                   // this thread's h: cols q+8m, q+8m+4
    float* us = (float*)(sm + OFF_US);

    for (int gi = 0; gi < 4; ++gi) {
        // ---- mainloop: C = A @ W via bf16-split mma.sync ----
        float C[2][4][4];
#pragma unroll
        for (int mt = 0; mt < 2; ++mt)
#pragma unroll
            for (int nt = 0; nt < 4; ++nt)
#pragma unroll
                for (int e2 = 0; e2 < 4; ++e2) C[mt][nt][e2] = 0.0f;

#pragma unroll
        for (int ks = 0; ks < 8; ++ks) {
            const int khalf = ks >> 2, kc0 = (ks & 3) * 16;
            uint32_t bh[4][2], bl[4][2];
#pragma unroll
            for (int pr = 0; pr < 2; ++pr) {
                int rb = 32 * wn + 16 * pr + b_r;
                uint32_t off = khalf * 16384 + (uint32_t)swz128(rb * 128 + (kc0 + b_koff) * 2);
                ldsm4(bh[2*pr][0], bh[2*pr][1], bh[2*pr+1][0], bh[2*pr+1][1],
                      sbase + OFF_BHI + off);
                ldsm4(bl[2*pr][0], bl[2*pr][1], bl[2*pr+1][0], bl[2*pr+1][1],
                      sbase + OFF_BLO + off);
            }
#pragma unroll
            for (int mt = 0; mt < 2; ++mt) {
                int ra = 32 * wm + 16 * mt + a_r;
                uint32_t off = khalf * 16384 + (uint32_t)swz128(ra * 128 + (kc0 + a_koff) * 2);
                uint32_t ah[4], al[4];
                ldsm4(ah[0], ah[1], ah[2], ah[3], sbase + OFF_AHI + off);
                ldsm4(al[0], al[1], al[2], al[3], sbase + OFF_ALO + off);
#pragma unroll
                for (int nt = 0; nt < 4; ++nt) {
                    mma_bf16(C[mt][nt], ah, bh[nt]);
                    mma_bf16(C[mt][nt], ah, bl[nt]);
                    mma_bf16(C[mt][nt], al, bh[nt]);
                }
            }
        }

        // ---- fragment epilogue: +bias (tanh for gi>0) -> us ----
        const float* biasL = (const float*)(sm + OFF_BIAS) + gi * 128;
#pragma unroll
        for (int mt = 0; mt < 2; ++mt)
#pragma unroll
            for (int nt = 0; nt < 4; ++nt) {
                int col0 = 32 * wn + 8 * nt + 2 * (l & 3);
                float2 b2 = *(const float2*)&biasL[col0];
                float v0 = C[mt][nt][0] + b2.x, v1 = C[mt][nt][1] + b2.y;
                float v2 = C[mt][nt][2] + b2.x, v3 = C[mt][nt][3] + b2.y;
                if (gi > 0) {
                    v0 = fast_tanh(v0); v1 = fast_tanh(v1);
                    v2 = fast_tanh(v2); v3 = fast_tanh(v3);
                }
                int r = 32 * wm + 16 * mt + (l >> 2);
                *(float2*)&us[r * USP + col0]       = make_float2(v0, v1);
                *(float2*)&us[(r + 8) * USP + col0] = make_float2(v2, v3);
            }
        __syncthreads();

        if (gi < 3) stage_B(sm, gi + 1, t);   // overlap next-layer weight copy

        const float* urow = us + erow * USP + q;
        if (gi == 0) {
#pragma unroll
            for (int m = 0; m < 16; ++m) {
                float h0 = urow[8 * m], h1 = urow[8 * m + 4];
                hp[m] = pack2(h0, h1);
                write_A1(sm, erow, q + 8 * m, h0);
                write_A1(sm, erow, q + 8 * m + 4, h1);
            }
        } else {
            ull uP[16];
#pragma unroll
            for (int m = 0; m < 16; ++m) uP[m] = pack2(urow[8 * m], urow[8 * m + 4]);

            // Taylor moments S_k = sum u^k h, T_k = sum u^k  (packed pairs)
            const ull ONE2 = 0x3F8000003F800000ull;
            ull Sa[NK], Ta[NK];
#pragma unroll
            for (int k = 0; k < NK; ++k) { Sa[k] = 0ull; Ta[k] = 0ull; }
#pragma unroll
            for (int m = 0; m < 16; ++m) {
                ull pw = ONE2;
#pragma unroll
                for (int k = 0; k < NK; ++k) {
                    Sa[k] = fma2(pw, hp[m], Sa[k]);
                    Ta[k] = add2(Ta[k], pw);
                    pw = mul2(pw, uP[m]);
                }
            }
            float S[NK], T[NK];
#pragma unroll
            for (int k = 0; k < NK; ++k) {
                float s = plo(Sa[k]) + phi(Sa[k]);
                float tt = plo(Ta[k]) + phi(Ta[k]);
                s += __shfl_xor_sync(0xffffffffu, s, 1);
                s += __shfl_xor_sync(0xffffffffu, s, 2);
                tt += __shfl_xor_sync(0xffffffffu, tt, 1);
                tt += __shfl_xor_sync(0xffffffffu, tt, 2);
                S[k] = s * cf[k];
                T[k] = tt * cf[k];
            }
            ull S2[NK], T2[NK];
#pragma unroll
            for (int k = 0; k < NK; ++k) {
                S2[k] = pack2(S[k], S[k]);
                T2[k] = pack2(T[k], T[k]);
            }
            // Horner: y = h + N(u)/D(u); accumulate LN stats
            float sum = 0.0f, sq = 0.0f;
            ull yP[16];
#pragma unroll
            for (int m = 0; m < 16; ++m) {
                ull N = S2[NK - 1], D = T2[NK - 1];
#pragma unroll
                for (int k = NK - 2; k >= 0; --k) {
                    N = fma2(N, uP[m], S2[k]);
                    D = fma2(D, uP[m], T2[k]);
                }
                float y0 = plo(hp[m]) + __fdividef(plo(N), plo(D));
                float y1 = phi(hp[m]) + __fdividef(phi(N), phi(D));
                yP[m] = pack2(y0, y1);
                sum += y0 + y1;
                sq = fmaf(y0, y0, sq);
                sq = fmaf(y1, y1, sq);
            }
            sum += __shfl_xor_sync(0xffffffffu, sum, 1);
            sum += __shfl_xor_sync(0xffffffffu, sum, 2);
            sq  += __shfl_xor_sync(0xffffffffu, sq, 1);
            sq  += __shfl_xor_sync(0xffffffffu, sq, 2);
            float mu = sum * (1.0f / H);
            float rs = rsqrtf(sq * (1.0f / H) - mu * mu + EPS);
            const float* gam = (const float*)(sm + OFF_GAM) + (gi - 1) * 128;
            const float* bet = (const float*)(sm + OFF_BET) + (gi - 1) * 128;
#pragma unroll
            for (int m = 0; m < 16; ++m) {
                int c0 = q + 8 * m, c1 = c0 + 4;
                float h0 = (plo(yP[m]) - mu) * rs * gam[c0] + bet[c0];
                float h1 = (phi(yP[m]) - mu) * rs * gam[c1] + bet[c1];
                hp[m] = pack2(h0, h1);
                if (gi < 3) { write_A1(sm, erow, c0, h0); write_A1(sm, erow, c1, h1); }
            }
        }
        __syncthreads();
    }

    // ---- classifier: logits = h @ W_c + b_c ----
    {
        const float* wc = (const float*)(sm + OFF_WC);
        float a[10];
#pragma unroll
        for (int c = 0; c < 10; ++c) a[c] = 0.0f;
#pragma unroll
        for (int m = 0; m < 16; ++m) {
#pragma unroll
            for (int pp = 0; pp < 2; ++pp) {
                int col = q + 8 * m + 4 * pp;
                float hv = pp ? phi(hp[m]) : plo(hp[m]);
                const float4* wr = (const float4*)&wc[col * 12];
                float4 w0 = wr[0], w1 = wr[1], w2 = wr[2];
                a[0] = fmaf(hv, w0.x, a[0]);  a[1] = fmaf(hv, w0.y, a[1]);
                a[2] = fmaf(hv, w0.z, a[2]);  a[3] = fmaf(hv, w0.w, a[3]);
                a[4] = fmaf(hv, w1.x, a[4]);  a[5] = fmaf(hv, w1.y, a[5]);
                a[6] = fmaf(hv, w1.z, a[6]);  a[7] = fmaf(hv, w1.w, a[7]);
                a[8] = fmaf(hv, w2.x, a[8]);  a[9] = fmaf(hv, w2.y, a[9]);
            }
        }
#pragma unroll
        for (int c = 0; c < NC; ++c) {
            a[c] += __shfl_xor_sync(0xffffffffu, a[c], 1);
            a[c] += __shfl_xor_sync(0xffffffffu, a[c], 2);
        }
        if (q == 0) {
            const float* bc = (const float*)(sm + OFF_BC);
#pragma unroll
            for (int c = 0; c < NC; ++c)
                out[(row0 + erow) * NC + c] = a[c] + bc[c];
        }
    }
}

}  // namespace

extern "C" void kernel_launch(void* const* d_in, const int* in_sizes, int n_in,
                              void* d_out, int out_size)
{
    const float* x     = (const float*)d_in[0];
    const float* W_in  = (const float*)d_in[1];
    const float* b_in  = (const float*)d_in[2];
    const float* W_att = (const float*)d_in[3];
    const float* b_att = (const float*)d_in[4];
    const float* gamma = (const float*)d_in[5];
    const float* beta  = (const float*)d_in[6];
    const float* W_c   = (const float*)d_in[7];
    const float* b_c   = (const float*)d_in[8];
    float* out = (float*)d_out;

    convert_weights<<<256, 256>>>(W_in, W_att);

    const int B = in_sizes[0] / H;
    const int grid = B / 128;                 // 16384/128 = 128 CTAs, single wave

    cudaFuncSetAttribute(fused_kernel,
                         cudaFuncAttributeMaxDynamicSharedMemorySize, SMEM_BYTES);
    fused_kernel<<<grid, NT, SMEM_BYTES>>>(x, b_in, b_att, gamma, beta, W_c, b_c, out);
}

// round 7
// speedup vs baseline: 2.8213x; 1.2090x over previous
#include <cuda_runtime.h>
#include <cuda_bf16.h>
#include <stdint.h>
#include <math.h>

namespace {
typedef unsigned long long ull;

constexpr int H = 128, TB = 64, NT = 256, NC = 10, NK = 10;
constexpr float EPS = 1e-5f;
constexpr int USP = 132;                     // us row pitch (floats)

// ---- SMEM byte offsets (from 1024-aligned base) ----
constexpr int OFF_AHI  = 0;                        // bf16 A-hi tile 64x128 (8KB x2 halves)
constexpr int OFF_ALO  = 16384;                    // bf16 A-lo
constexpr int OFF_US   = 32768;                    // float[64][USP]
constexpr int OFF_WC   = OFF_US + TB * USP * 4;    // float[128][12]
constexpr int OFF_BIAS = OFF_WC + 128 * 12 * 4;    // float[4][128]
constexpr int OFF_GAM  = OFF_BIAS + 4 * 128 * 4;   // float[3][128]
constexpr int OFF_BET  = OFF_GAM + 3 * 128 * 4;
constexpr int OFF_BC   = OFF_BET + 3 * 128 * 4;    // float[16]
constexpr int SMEM_BYTES = OFF_BC + 64 + 1024;

// Weights pre-converted to mma-fragment order:
// index = ((layer*16 + ntile)*8 + kstep)*32 + lane, payload = {b0hi,b1hi,b0lo,b1lo}
constexpr int NFRAG = 4 * 16 * 8 * 32;
__device__ uint4 g_bfrag[NFRAG];

__host__ __device__ __forceinline__ int swz128(int b) { return b ^ ((b >> 3) & 0x70); }

__device__ __forceinline__ uint32_t smem_u32(const void* p) {
    uint32_t a;
    asm("{ .reg .u64 t; cvta.to.shared.u64 t, %1; cvt.u32.u64 %0, t; }" : "=r"(a) : "l"(p));
    return a;
}

// ---- f32x2 packed math ----
__device__ __forceinline__ ull fma2(ull a, ull b, ull c) {
    ull d; asm("fma.rn.f32x2 %0, %1, %2, %3;" : "=l"(d) : "l"(a), "l"(b), "l"(c)); return d;
}
__device__ __forceinline__ ull add2(ull a, ull b) {
    ull d; asm("add.rn.f32x2 %0, %1, %2;" : "=l"(d) : "l"(a), "l"(b)); return d;
}
__device__ __forceinline__ ull mul2(ull a, ull b) {
    ull d; asm("mul.rn.f32x2 %0, %1, %2;" : "=l"(d) : "l"(a), "l"(b)); return d;
}
__device__ __forceinline__ ull pack2(float lo, float hi) {
    ull d; asm("mov.b64 %0, {%1, %2};" : "=l"(d) : "f"(lo), "f"(hi)); return d;
}
__device__ __forceinline__ float plo(ull v) { return __uint_as_float((unsigned)v); }
__device__ __forceinline__ float phi(ull v) { return __uint_as_float((unsigned)(v >> 32)); }

__device__ __forceinline__ void ldsm4(uint32_t& r0, uint32_t& r1, uint32_t& r2,
                                      uint32_t& r3, uint32_t addr) {
    asm volatile("ldmatrix.sync.aligned.m8n8.x4.shared.b16 {%0,%1,%2,%3}, [%4];"
                 : "=r"(r0), "=r"(r1), "=r"(r2), "=r"(r3) : "r"(addr));
}
__device__ __forceinline__ void mma_bf16(float* c, const uint32_t* a,
                                         uint32_t b0, uint32_t b1) {
    asm volatile("mma.sync.aligned.m16n8k16.row.col.f32.bf16.bf16.f32 "
                 "{%0,%1,%2,%3}, {%4,%5,%6,%7}, {%8,%9}, {%0,%1,%2,%3};"
                 : "+f"(c[0]), "+f"(c[1]), "+f"(c[2]), "+f"(c[3])
                 : "r"(a[0]), "r"(a[1]), "r"(a[2]), "r"(a[3]), "r"(b0), "r"(b1));
}

__device__ __forceinline__ float fast_tanh(float x) {
    float a = fabsf(x);
    float e = __expf(-2.0f * a);
    float t = __fdividef(1.0f - e, 1.0f + e);
    return copysignf(t, x);
}
__device__ __forceinline__ void split_bf16(float v, __nv_bfloat16& hi, __nv_bfloat16& lo) {
    hi = __float2bfloat16(v);
    lo = __float2bfloat16(v - __bfloat162float(hi));
}
__device__ __forceinline__ uint32_t packbf2(__nv_bfloat16 a, __nv_bfloat16 b) {
    __nv_bfloat162 p; p.x = a; p.y = b;
    return *reinterpret_cast<uint32_t*>(&p);
}

// One-time: W[k][n] fp32 -> per-lane mma B fragments (hi+lo packed in one uint4).
// m16n8k16 B fragment: lane l, reg0 holds B[2*(l%4)+{0,1}][l/4], reg1 k+8.
__global__ void convert_weights(const float* __restrict__ W_in,
                                const float* __restrict__ W_att) {
    int gidx = blockIdx.x * blockDim.x + threadIdx.x;   // 16384
    if (gidx >= NFRAG) return;
    int lane = gidx & 31;
    int s    = (gidx >> 5) & 7;
    int nt   = (gidx >> 8) & 15;
    int layer = gidx >> 12;
    const float* W = (layer == 0) ? W_in : (W_att + (size_t)(layer - 1) * H * H);
    int n  = 8 * nt + (lane >> 2);
    int k0 = 16 * s + 2 * (lane & 3);
    float v00 = W[(k0 + 0) * H + n], v01 = W[(k0 + 1) * H + n];
    float v10 = W[(k0 + 8) * H + n], v11 = W[(k0 + 9) * H + n];
    __nv_bfloat16 h00, l00, h01, l01, h10, l10, h11, l11;
    split_bf16(v00, h00, l00); split_bf16(v01, h01, l01);
    split_bf16(v10, h10, l10); split_bf16(v11, h11, l11);
    uint4 f;
    f.x = packbf2(h00, h01);   // b0 hi
    f.y = packbf2(h10, h11);   // b1 hi
    f.z = packbf2(l00, l01);   // b0 lo
    f.w = packbf2(l10, l11);   // b1 lo
    g_bfrag[gidx] = f;
}

__device__ __forceinline__ void write_A1(char* sm, int row, int col, float v) {
    int byz = (col >> 6) * 8192 + swz128(row * 128 + (col & 63) * 2);
    __nv_bfloat16 hi, lo;
    split_bf16(v, hi, lo);
    *(__nv_bfloat16*)(sm + OFF_AHI + byz) = hi;
    *(__nv_bfloat16*)(sm + OFF_ALO + byz) = lo;
}

__global__ void __launch_bounds__(NT, 2)
fused_kernel(const float* __restrict__ x,
             const float* __restrict__ b_in,
             const float* __restrict__ b_att,
             const float* __restrict__ gamma_,
             const float* __restrict__ beta_,
             const float* __restrict__ W_c,
             const float* __restrict__ b_c,
             float* __restrict__ out)
{
    extern __shared__ char smraw[];
    char* sm = (char*)(((uintptr_t)smraw + 1023) & ~(uintptr_t)1023);
    const int t = threadIdx.x, l = t & 31, w = t >> 5;
    const int wm = w & 1, wn = w >> 1;           // warp tile: rows 32wm.., cols 32wn..
    const int erow = t >> 2, q = t & 3;          // epilogue: row (0..63), col residue
    const long row0 = (long)blockIdx.x * TB;
    const uint32_t sbase = smem_u32(sm);

    // ldmatrix per-lane address components
    const int a_r = l & 15;
    const int a_koff = (l >> 4) * 8;

    // ---- init: x -> A tiles (64 rows), params ----
#pragma unroll
    for (int it = 0; it < 8; ++it) {
        int fidx = t + NT * it;                  // 2048 float4s
        int r = fidx >> 5, c4 = fidx & 31;
        float4 xv = *(const float4*)&x[(row0 + r) * H + 4 * c4];
        int sz = (c4 >> 4) * 8192 + swz128(r * 128 + ((4 * c4) & 63) * 2);
        __nv_bfloat16 h0, h1, h2, h3, l0, l1, l2, l3;
        split_bf16(xv.x, h0, l0); split_bf16(xv.y, h1, l1);
        split_bf16(xv.z, h2, l2); split_bf16(xv.w, h3, l3);
        *(uint32_t*)(sm + OFF_AHI + sz)     = packbf2(h0, h1);
        *(uint32_t*)(sm + OFF_AHI + sz + 4) = packbf2(h2, h3);
        *(uint32_t*)(sm + OFF_ALO + sz)     = packbf2(l0, l1);
        *(uint32_t*)(sm + OFF_ALO + sz + 4) = packbf2(l2, l3);
    }
    if (t < H) {
        ((float*)(sm + OFF_BIAS))[t] = b_in[t];
#pragma unroll
        for (int i = 0; i < 3; ++i) {
            ((float*)(sm + OFF_BIAS))[(i + 1) * 128 + t] = b_att[i * H + t];
            ((float*)(sm + OFF_GAM))[i * 128 + t] = gamma_[i * H + t];
            ((float*)(sm + OFF_BET))[i * 128 + t] = beta_[i * H + t];
        }
    }
    for (int idx = t; idx < 128 * 12; idx += NT) {
        int col = idx / 12, c = idx % 12;
        ((float*)(sm + OFF_WC))[idx] = (c < NC) ? W_c[col * NC + c] : 0.0f;
    }
    if (t < NC) ((float*)(sm + OFF_BC))[t] = b_c[t];
    __syncthreads();

    const float cf[NK] = {
        1.0f, 1.0f, 0.5f,
        1.6666666666666666e-1f, 4.1666666666666664e-2f, 8.3333333333333332e-3f,
        1.3888888888888889e-3f, 1.9841269841269841e-4f, 2.4801587301587302e-5f,
        2.7557319223985893e-6f };

    ull hp[16];                                  // this thread's h: cols q+8m, q+8m+4
    float* us = (float*)(sm + OFF_US);

    for (int gi = 0; gi < 4; ++gi) {
        // ---- mainloop: C = A @ W, bf16-split, B streamed from L2 in fragment order ----
        float C[2][4][4];
#pragma unroll
        for (int mt = 0; mt < 2; ++mt)
#pragma unroll
            for (int nt = 0; nt < 4; ++nt)
#pragma unroll
                for (int e2 = 0; e2 < 4; ++e2) C[mt][nt][e2] = 0.0f;

        const uint4* bf_base = g_bfrag + ((gi * 16 + 4 * wn) * 8) * 32 + l;
#pragma unroll
        for (int s = 0; s < 8; ++s) {
            uint4 f[4];
#pragma unroll
            for (int j = 0; j < 4; ++j)
                f[j] = __ldg(bf_base + (j * 8 + s) * 32);

            const int khalf = s >> 2, kc0 = (s & 3) * 16;
#pragma unroll
            for (int mt = 0; mt < 2; ++mt) {
                int ra = 32 * wm + 16 * mt + a_r;
                uint32_t off = khalf * 8192 + (uint32_t)swz128(ra * 128 + (kc0 + a_koff) * 2);
                uint32_t ah[4], al[4];
                ldsm4(ah[0], ah[1], ah[2], ah[3], sbase + OFF_AHI + off);
                ldsm4(al[0], al[1], al[2], al[3], sbase + OFF_ALO + off);
#pragma unroll
                for (int j = 0; j < 4; ++j) {
                    mma_bf16(C[mt][j], ah, f[j].x, f[j].y);   // Ahi*Bhi
                    mma_bf16(C[mt][j], ah, f[j].z, f[j].w);   // Ahi*Blo
                    mma_bf16(C[mt][j], al, f[j].x, f[j].y);   // Alo*Bhi
                }
            }
        }

        // ---- fragment epilogue: +bias (tanh for gi>0) -> us ----
        const float* biasL = (const float*)(sm + OFF_BIAS) + gi * 128;
#pragma unroll
        for (int mt = 0; mt < 2; ++mt)
#pragma unroll
            for (int nt = 0; nt < 4; ++nt) {
                int col0 = 32 * wn + 8 * nt + 2 * (l & 3);
                float2 b2 = *(const float2*)&biasL[col0];
                float v0 = C[mt][nt][0] + b2.x, v1 = C[mt][nt][1] + b2.y;
                float v2 = C[mt][nt][2] + b2.x, v3 = C[mt][nt][3] + b2.y;
                if (gi > 0) {
                    v0 = fast_tanh(v0); v1 = fast_tanh(v1);
                    v2 = fast_tanh(v2); v3 = fast_tanh(v3);
                }
                int r = 32 * wm + 16 * mt + (l >> 2);
                *(float2*)&us[r * USP + col0]       = make_float2(v0, v1);
                *(float2*)&us[(r + 8) * USP + col0] = make_float2(v2, v3);
            }
        __syncthreads();

        const float* urow = us + erow * USP + q;
        if (gi == 0) {
#pragma unroll
            for (int m = 0; m < 16; ++m) {
                float h0 = urow[8 * m], h1 = urow[8 * m + 4];
                hp[m] = pack2(h0, h1);
                write_A1(sm, erow, q + 8 * m, h0);
                write_A1(sm, erow, q + 8 * m + 4, h1);
            }
        } else {
            ull uP[16];
#pragma unroll
            for (int m = 0; m < 16; ++m) uP[m] = pack2(urow[8 * m], urow[8 * m + 4]);

            // Taylor moments S_k = sum u^k h, T_k = sum u^k (packed pairs)
            const ull ONE2 = 0x3F8000003F800000ull;
            ull Sa[NK], Ta[NK];
#pragma unroll
            for (int k = 0; k < NK; ++k) { Sa[k] = 0ull; Ta[k] = 0ull; }
#pragma unroll
            for (int m = 0; m < 16; ++m) {
                ull pw = ONE2;
#pragma unroll
                for (int k = 0; k < NK; ++k) {
                    Sa[k] = fma2(pw, hp[m], Sa[k]);
                    Ta[k] = add2(Ta[k], pw);
                    pw = mul2(pw, uP[m]);
                }
            }
            float S[NK], T[NK];
#pragma unroll
            for (int k = 0; k < NK; ++k) {
                float s = plo(Sa[k]) + phi(Sa[k]);
                float tt = plo(Ta[k]) + phi(Ta[k]);
                s += __shfl_xor_sync(0xffffffffu, s, 1);
                s += __shfl_xor_sync(0xffffffffu, s, 2);
                tt += __shfl_xor_sync(0xffffffffu, tt, 1);
                tt += __shfl_xor_sync(0xffffffffu, tt, 2);
                S[k] = s * cf[k];
                T[k] = tt * cf[k];
            }
            ull S2[NK], T2[NK];
#pragma unroll
            for (int k = 0; k < NK; ++k) {
                S2[k] = pack2(S[k], S[k]);
                T2[k] = pack2(T[k], T[k]);
            }
            // Horner: y = h + N(u)/D(u); LN stats; overwrite hp with y
            float sum = 0.0f, sq = 0.0f;
#pragma unroll
            for (int m = 0; m < 16; ++m) {
                ull N = S2[NK - 1], D = T2[NK - 1];
#pragma unroll
                for (int k = NK - 2; k >= 0; --k) {
                    N = fma2(N, uP[m], S2[k]);
                    D = fma2(D, uP[m], T2[k]);
                }
                float y0 = plo(hp[m]) + __fdividef(plo(N), plo(D));
                float y1 = phi(hp[m]) + __fdividef(phi(N), phi(D));
                hp[m] = pack2(y0, y1);
                sum += y0 + y1;
                sq = fmaf(y0, y0, sq);
                sq = fmaf(y1, y1, sq);
            }
            sum += __shfl_xor_sync(0xffffffffu, sum, 1);
            sum += __shfl_xor_sync(0xffffffffu, sum, 2);
            sq  += __shfl_xor_sync(0xffffffffu, sq, 1);
            sq  += __shfl_xor_sync(0xffffffffu, sq, 2);
            float mu = sum * (1.0f / H);
            float rs = rsqrtf(sq * (1.0f / H) - mu * mu + EPS);
            const float* gam = (const float*)(sm + OFF_GAM) + (gi - 1) * 128;
            const float* bet = (const float*)(sm + OFF_BET) + (gi - 1) * 128;
#pragma unroll
            for (int m = 0; m < 16; ++m) {
                int c0 = q + 8 * m, c1 = c0 + 4;
                float h0 = (plo(hp[m]) - mu) * rs * gam[c0] + bet[c0];
                float h1 = (phi(hp[m]) - mu) * rs * gam[c1] + bet[c1];
                hp[m] = pack2(h0, h1);
                if (gi < 3) { write_A1(sm, erow, c0, h0); write_A1(sm, erow, c1, h1); }
            }
        }
        __syncthreads();
    }

    // ---- classifier: logits = h @ W_c + b_c ----
    {
        const float* wc = (const float*)(sm + OFF_WC);
        float a[10];
#pragma unroll
        for (int c = 0; c < 10; ++c) a[c] = 0.0f;
#pragma unroll
        for (int m = 0; m < 16; ++m) {
#pragma unroll
            for (int pp = 0; pp < 2; ++pp) {
                int col = q + 8 * m + 4 * pp;
                float hv = pp ? phi(hp[m]) : plo(hp[m]);
                const float4* wr = (const float4*)&wc[col * 12];
                float4 w0 = wr[0], w1 = wr[1], w2 = wr[2];
                a[0] = fmaf(hv, w0.x, a[0]);  a[1] = fmaf(hv, w0.y, a[1]);
                a[2] = fmaf(hv, w0.z, a[2]);  a[3] = fmaf(hv, w0.w, a[3]);
                a[4] = fmaf(hv, w1.x, a[4]);  a[5] = fmaf(hv, w1.y, a[5]);
                a[6] = fmaf(hv, w1.z, a[6]);  a[7] = fmaf(hv, w1.w, a[7]);
                a[8] = fmaf(hv, w2.x, a[8]);  a[9] = fmaf(hv, w2.y, a[9]);
            }
        }
#pragma unroll
        for (int c = 0; c < NC; ++c) {
            a[c] += __shfl_xor_sync(0xffffffffu, a[c], 1);
            a[c] += __shfl_xor_sync(0xffffffffu, a[c], 2);
        }
        if (q == 0) {
            const float* bc = (const float*)(sm + OFF_BC);
#pragma unroll
            for (int c = 0; c < NC; ++c)
                out[(row0 + erow) * NC + c] = a[c] + bc[c];
        }
    }
}

}  // namespace

extern "C" void kernel_launch(void* const* d_in, const int* in_sizes, int n_in,
                              void* d_out, int out_size)
{
    const float* x     = (const float*)d_in[0];
    const float* W_in  = (const float*)d_in[1];
    const float* b_in  = (const float*)d_in[2];
    const float* b_att = (const float*)d_in[4];
    const float* W_att = (const float*)d_in[3];
    const float* gamma = (const float*)d_in[5];
    const float* beta  = (const float*)d_in[6];
    const float* W_c   = (const float*)d_in[7];
    const float* b_c   = (const float*)d_in[8];
    float* out = (float*)d_out;

    convert_weights<<<64, 256>>>(W_in, W_att);

    const int B = in_sizes[0] / H;
    const int grid = B / TB;                  // 16384/64 = 256 CTAs, 2 per SM

    cudaFuncSetAttribute(fused_kernel,
                         cudaFuncAttributeMaxDynamicSharedMemorySize, SMEM_BYTES);
    fused_kernel<<<grid, NT, SMEM_BYTES>>>(x, b_in, b_att, gamma, beta, W_c, b_c, out);
}